// round 5
// baseline (speedup 1.0000x reference)
#include <cuda_runtime.h>
#include <cuda_bf16.h>
#include <cstdint>
#include <math.h>

#define ENC 2048
#define DEC 512
#define ATTD 512
#define BATCH 256
#define LSEQ 196
#define MROWS (BATCH * LSEQ)      // 50176
#define TILE_M 128
#define NCTA (MROWS / TILE_M)     // 392
#define KBLK 32
#define NKB (ENC / KBLK)          // 64
#define NB_CHUNKS 2               // 512 / 256
#define NSTG 4
#define XSTG 16384                // 128 rows x 32k x 2B x 2(hi/lo)
#define WSTG 32768                // 256 rows x 32k x 2B x 2(hi/lo)
#define WBASE (NSTG * XSTG)       // 65536
#define DYN_BYTES (WBASE + NSTG * WSTG + 128)  // 196736
#define XLO_OFF ((size_t)MROWS * ENC * 2)      // byte offset of lo plane in g_Xc

// ---------------- scratch globals ----------------
__device__ float g_att2[BATCH * ATTD];
__device__ float g_gate[BATCH];
__device__ float g_att[MROWS];
// W transposed + bf16-split: [hl][n=512][k=2048] bf16
__device__ __align__(16) unsigned char g_Wt[2u * 512u * 2048u * 2u];
// x bf16-split: [hl][m=50176][k=2048] bf16 (hi plane then lo plane)
__device__ __align__(16) unsigned char g_Xc[2ull * MROWS * ENC * 2ull];

// ---------------- helpers ----------------
__device__ __forceinline__ uint32_t smem_u32(const void* p) {
    uint32_t a;
    asm("{ .reg .u64 t; cvta.to.shared.u64 t, %1; cvt.u32.u64 %0, t; }" : "=r"(a) : "l"(p));
    return a;
}
__device__ __forceinline__ uint32_t pack2(float a, float b) {
    __nv_bfloat162 t = __floats2bfloat162_rn(a, b);
    return *reinterpret_cast<uint32_t*>(&t);
}
#define LDSM_X4(r, addr) \
    asm volatile("ldmatrix.sync.aligned.m8n8.x4.shared.b16 {%0,%1,%2,%3}, [%4];" \
        : "=r"((r)[0]), "=r"((r)[1]), "=r"((r)[2]), "=r"((r)[3]) : "r"(addr))
#define MMA_BF16(c, a, b) \
    asm volatile("mma.sync.aligned.m16n8k16.row.col.f32.bf16.bf16.f32 " \
        "{%0,%1,%2,%3}, {%4,%5,%6,%7}, {%8,%9}, {%0,%1,%2,%3};" \
        : "+f"((c)[0]), "+f"((c)[1]), "+f"((c)[2]), "+f"((c)[3]) \
        : "r"((a)[0]), "r"((a)[1]), "r"((a)[2]), "r"((a)[3]), "r"((b)[0]), "r"((b)[1]))
#define CP_ASYNC16(dst, src) \
    asm volatile("cp.async.ca.shared.global [%0], [%1], 16;" :: "r"(dst), "l"(src) : "memory")
#define CP_COMMIT() asm volatile("cp.async.commit_group;" ::: "memory")
#define CP_WAIT2()  asm volatile("cp.async.wait_group 2;" ::: "memory")
#define CP_WAIT0()  asm volatile("cp.async.wait_group 0;" ::: "memory")

// ---------------------------------------------------------------------------
// prep_x: x fp32 [m][k] -> g_Xc bf16 hi/lo planes. One block per row.
// ---------------------------------------------------------------------------
__global__ __launch_bounds__(256) void prep_x(const float* __restrict__ x) {
    const size_t row = blockIdx.x;
    const int t = threadIdx.x;
    const float4* src = reinterpret_cast<const float4*>(x + row * ENC) + t * 2;
    float4 a = src[0], b = src[1];
    float e[8] = {a.x, a.y, a.z, a.w, b.x, b.y, b.z, b.w};
    uint32_t hw[4], lw[4];
#pragma unroll
    for (int q = 0; q < 4; q++) {
        float v0 = e[2 * q], v1 = e[2 * q + 1];
        float h0 = __bfloat162float(__float2bfloat16_rn(v0));
        float h1 = __bfloat162float(__float2bfloat16_rn(v1));
        hw[q] = pack2(h0, h1);
        lw[q] = pack2(v0 - h0, v1 - h1);
    }
    *reinterpret_cast<uint4*>(g_Xc + row * (ENC * 2) + t * 16) =
        make_uint4(hw[0], hw[1], hw[2], hw[3]);
    *reinterpret_cast<uint4*>(g_Xc + XLO_OFF + row * (ENC * 2) + t * 16) =
        make_uint4(lw[0], lw[1], lw[2], lw[3]);
}

// ---------------------------------------------------------------------------
// prep_w: W_enc [2048 k][512 n] fp32 -> g_Wt bf16 [hl][n][k]
// ---------------------------------------------------------------------------
__global__ __launch_bounds__(256) void prep_w(const float* __restrict__ W_enc) {
    __shared__ float tile[64][65];
    const int k0 = blockIdx.x * 64, n0 = blockIdx.y * 64;
    const int tid = threadIdx.x;
    for (int i = tid; i < 64 * 64; i += 256) {
        int kk = i >> 6, nn = i & 63;
        tile[kk][nn] = W_enc[(size_t)(k0 + kk) * ATTD + n0 + nn];
    }
    __syncthreads();
    for (int i = tid; i < 1024; i += 256) {
        int hl = i >> 9, rem = i & 511;
        int nn = rem >> 3, ch = rem & 7;
        uint32_t w[4];
#pragma unroll
        for (int j = 0; j < 4; j++) {
            float v0 = tile[ch * 8 + 2 * j][nn], v1 = tile[ch * 8 + 2 * j + 1][nn];
            float h0 = __bfloat162float(__float2bfloat16_rn(v0));
            float h1 = __bfloat162float(__float2bfloat16_rn(v1));
            w[j] = hl ? pack2(v0 - h0, v1 - h1) : pack2(h0, h1);
        }
        *reinterpret_cast<uint4*>(g_Wt + (size_t)hl * 2097152 +
                                  (size_t)(n0 + nn) * 4096 + (size_t)(k0 + ch * 8) * 2) =
            make_uint4(w[0], w[1], w[2], w[3]);
    }
}

// ---------------------------------------------------------------------------
// att2 + gate
// ---------------------------------------------------------------------------
__global__ __launch_bounds__(256) void att2_kernel(
    const float* __restrict__ h, const float* __restrict__ W_dec,
    const float* __restrict__ b_dec, const float* __restrict__ b_enc,
    const float* __restrict__ W_beta, const float* __restrict__ b_beta) {
    int b = blockIdx.x, t = threadIdx.x;
    __shared__ float hs[DEC];
    __shared__ float red[256];
    hs[t] = h[b * DEC + t];
    hs[t + 256] = h[b * DEC + t + 256];
    __syncthreads();
    float acc0 = 0.f, acc1 = 0.f;
#pragma unroll 8
    for (int k = 0; k < DEC; k++) {
        float hv = hs[k];
        acc0 += hv * W_dec[k * ATTD + t];
        acc1 += hv * W_dec[k * ATTD + t + 256];
    }
    g_att2[b * ATTD + t] = acc0 + b_dec[t] + b_enc[t];
    g_att2[b * ATTD + t + 256] = acc1 + b_dec[t + 256] + b_enc[t + 256];
    float p = hs[t] * W_beta[t] + hs[t + 256] * W_beta[t + 256];
    red[t] = p;
    __syncthreads();
    for (int s = 128; s > 0; s >>= 1) {
        if (t < s) red[t] += red[t + s];
        __syncthreads();
    }
    if (t == 0) g_gate[b] = 1.f / (1.f + expf(-(red[0] + b_beta[0])));
}

// ---------------------------------------------------------------------------
// Main GEMM: 3-pass bf16 mma.sync, 4-stage all-cp.async pipeline.
// 8 warps = 2(m) x 4(n); warp tile m64 x n64. N chunks of 256 (2 passes).
// ---------------------------------------------------------------------------
__global__ __launch_bounds__(256, 1) void att_gemm_mma(const float* __restrict__ W_full) {
    extern __shared__ unsigned char dynraw[];
    __shared__ float wf_s[ATTD];
    __shared__ float att_acc[TILE_M];

    const int tid = threadIdx.x;
    const int lane = tid & 31;
    const int wid = tid >> 5;
    const int wm = wid >> 2;   // 0..1
    const int wn = wid & 3;    // 0..3
    const int row0 = blockIdx.x * TILE_M;

    uint32_t rawb = smem_u32(dynraw);
    uint32_t dynb = (rawb + 127u) & ~127u;

    for (int i = tid; i < ATTD; i += 256) wf_s[i] = W_full[i];
    if (tid < TILE_M) att_acc[tid] = 0.f;
    __syncthreads();

    // ---- x loader: thread -> (row xm, k-half xh2 of 16 elems); 4 cp.async/stage ----
    const int xm = tid >> 1, xh2 = tid & 1;
    const int xsw = (xm >> 1) & 3;
    const size_t xrow_off = (size_t)(row0 + xm) * (ENC * 2);

    // ldmatrix lane geometry (2m x 4n)
    const int a_r = wm * 64 + (lane & 7) + (lane & 8);
    const int a_hi = lane >> 4;
    const int b_r = wn * 64 + (lane & 7) + ((lane >> 1) & 8);
    const int b_hi = (lane >> 3) & 1;

    for (int nb = 0; nb < NB_CHUNKS; nb++) {
        float acc[4][8][4];
#pragma unroll
        for (int mt = 0; mt < 4; mt++)
#pragma unroll
            for (int nt = 0; nt < 8; nt++)
#pragma unroll
                for (int q = 0; q < 4; q++) acc[mt][nt][q] = 0.f;

        // ---- prologue: stages 0..2 (x + W in one group per stage) ----
#pragma unroll
        for (int p = 0; p < 3; p++) {
#pragma unroll
            for (int hl = 0; hl < 2; hl++)
#pragma unroll
                for (int j = 0; j < 2; j++) {
                    int c = xh2 * 2 + j;
                    uint32_t dst = dynb + p * XSTG + hl * 8192 + xm * 64 +
                                   ((c ^ xsw) << 4);
                    const unsigned char* src = g_Xc + hl * XLO_OFF + xrow_off +
                        (size_t)(p * KBLK + c * 8) * 2;
                    CP_ASYNC16(dst, src);
                }
#pragma unroll
            for (int hl = 0; hl < 2; hl++)
#pragma unroll
                for (int j = 0; j < 4; j++) {
                    int i = tid + 256 * j;
                    int row = i >> 2, c = i & 3;
                    uint32_t dst = dynb + WBASE + p * WSTG + hl * 16384 +
                                   row * 64 + ((c ^ ((row >> 1) & 3)) << 4);
                    const unsigned char* src = g_Wt + (size_t)hl * 2097152 +
                        (size_t)(nb * 256 + row) * 4096 + (size_t)(p * KBLK + c * 8) * 2;
                    CP_ASYNC16(dst, src);
                }
            CP_COMMIT();
        }

        for (int kblk = 0; kblk < NKB; kblk++) {
            CP_WAIT2();
            __syncthreads();   // stage kblk%4 ready; stage (kblk+3)%4 free

            // issue x+W for stage kblk+3 (or empty group)
            if (kblk + 3 < NKB) {
                const int st = (kblk + 3) & 3;
#pragma unroll
                for (int hl = 0; hl < 2; hl++)
#pragma unroll
                    for (int j = 0; j < 2; j++) {
                        int c = xh2 * 2 + j;
                        uint32_t dst = dynb + st * XSTG + hl * 8192 + xm * 64 +
                                       ((c ^ xsw) << 4);
                        const unsigned char* src = g_Xc + hl * XLO_OFF + xrow_off +
                            (size_t)((kblk + 3) * KBLK + c * 8) * 2;
                        CP_ASYNC16(dst, src);
                    }
#pragma unroll
                for (int hl = 0; hl < 2; hl++)
#pragma unroll
                    for (int j = 0; j < 4; j++) {
                        int i = tid + 256 * j;
                        int row = i >> 2, c = i & 3;
                        uint32_t dst = dynb + WBASE + st * WSTG + hl * 16384 +
                                       row * 64 + ((c ^ ((row >> 1) & 3)) << 4);
                        const unsigned char* src = g_Wt + (size_t)hl * 2097152 +
                            (size_t)(nb * 256 + row) * 4096 +
                            (size_t)((kblk + 3) * KBLK + c * 8) * 2;
                        CP_ASYNC16(dst, src);
                    }
            }
            CP_COMMIT();

            // ---- MMA on stage kblk%4 ----
            {
                const uint32_t xsb = dynb + (kblk & 3) * XSTG;
                const uint32_t wsb = dynb + WBASE + (kblk & 3) * WSTG;
#pragma unroll
                for (int ks = 0; ks < 2; ks++) {
                    uint32_t ah[4][4], al[4][4];
#pragma unroll
                    for (int mt = 0; mt < 4; mt++) {
                        int row = a_r + mt * 16;
                        uint32_t ad = xsb + row * 64 +
                                      (((ks * 2 + a_hi) ^ ((row >> 1) & 3)) << 4);
                        LDSM_X4(ah[mt], ad);
                        LDSM_X4(al[mt], ad + 8192);
                    }
#pragma unroll
                    for (int ntp = 0; ntp < 4; ntp++) {
                        int row = b_r + ntp * 16;
                        uint32_t bd = wsb + row * 64 +
                                      (((ks * 2 + b_hi) ^ ((row >> 1) & 3)) << 4);
                        uint32_t bh[4], bl[4];
                        LDSM_X4(bh, bd);
                        LDSM_X4(bl, bd + 16384);
#pragma unroll
                        for (int mt = 0; mt < 4; mt++) {
                            MMA_BF16(acc[mt][2 * ntp],     ah[mt], bh + 0);
                            MMA_BF16(acc[mt][2 * ntp + 1], ah[mt], bh + 2);
                            MMA_BF16(acc[mt][2 * ntp],     ah[mt], bl + 0);
                            MMA_BF16(acc[mt][2 * ntp + 1], ah[mt], bl + 2);
                            MMA_BF16(acc[mt][2 * ntp],     al[mt], bh + 0);
                            MMA_BF16(acc[mt][2 * ntp + 1], al[mt], bh + 2);
                        }
                    }
                }
            }
        }
        CP_WAIT0();
        __syncthreads();

        // ---- epilogue for this n-chunk ----
#pragma unroll
        for (int mt = 0; mt < 4; mt++)
#pragma unroll
            for (int rh = 0; rh < 2; rh++) {
                int ml = wm * 64 + mt * 16 + (lane >> 2) + rh * 8;
                int gm = row0 + ml;
                int b = gm / LSEQ;
                const float* a2 = g_att2 + (size_t)b * ATTD + nb * 256 + wn * 64;
                const float* wfp = wf_s + nb * 256 + wn * 64;
                float s = 0.f;
#pragma unroll
                for (int nt = 0; nt < 8; nt++) {
#pragma unroll
                    for (int e2 = 0; e2 < 2; e2++) {
                        int nn = nt * 8 + (lane & 3) * 2 + e2;
                        float v = acc[mt][nt][rh * 2 + e2] + __ldg(a2 + nn);
                        s += fmaxf(v, 0.f) * wfp[nn];
                    }
                }
                s += __shfl_xor_sync(0xFFFFFFFF, s, 1);
                s += __shfl_xor_sync(0xFFFFFFFF, s, 2);
                if ((lane & 3) == 0) atomicAdd(&att_acc[ml], s);
            }
        __syncthreads();
    }

    if (tid < TILE_M) g_att[row0 + tid] = att_acc[tid];
}

// ---------------------------------------------------------------------------
__global__ __launch_bounds__(256) void softmax_kernel(float* __restrict__ out_alpha) {
    int b = blockIdx.x, t = threadIdx.x;
    __shared__ float sred[256];
    float v = (t < LSEQ) ? g_att[b * LSEQ + t] : -1e30f;
    sred[t] = v;
    __syncthreads();
    for (int s = 128; s > 0; s >>= 1) {
        if (t < s) sred[t] = fmaxf(sred[t], sred[t + s]);
        __syncthreads();
    }
    float m = sred[0];
    __syncthreads();
    float e = (t < LSEQ) ? expf(v - m) : 0.f;
    sred[t] = e;
    __syncthreads();
    for (int s = 128; s > 0; s >>= 1) {
        if (t < s) sred[t] += sred[t + s];
        __syncthreads();
    }
    float inv = 1.f / sred[0];
    if (t < LSEQ) out_alpha[b * LSEQ + t] = e * inv;
}

__global__ __launch_bounds__(256) void z_kernel(
    const float* __restrict__ x, const float* __restrict__ alpha,
    float* __restrict__ out_z) {
    int b = blockIdx.y;
    int c4 = blockIdx.x * 256 + threadIdx.x;
    __shared__ float sal[LSEQ];
    for (int i = threadIdx.x; i < LSEQ; i += 256) sal[i] = alpha[b * LSEQ + i];
    __syncthreads();
    const float4* xp = reinterpret_cast<const float4*>(x + (size_t)b * LSEQ * ENC) + c4;
    float ax = 0.f, ay = 0.f, az = 0.f, aw = 0.f;
#pragma unroll 4
    for (int l = 0; l < LSEQ; l++) {
        float4 v = xp[(size_t)l * (ENC / 4)];
        float a = sal[l];
        ax += a * v.x; ay += a * v.y; az += a * v.z; aw += a * v.w;
    }
    float g = g_gate[b];
    float4 o;
    o.x = g * ax; o.y = g * ay; o.z = g * az; o.w = g * aw;
    reinterpret_cast<float4*>(out_z)[(size_t)b * (ENC / 4) + c4] = o;
}

// ---------------------------------------------------------------------------
extern "C" void kernel_launch(void* const* d_in, const int* in_sizes, int n_in,
                              void* d_out, int out_size) {
    const float* x      = (const float*)d_in[0];
    const float* h      = (const float*)d_in[1];
    const float* W_enc  = (const float*)d_in[2];
    const float* b_enc  = (const float*)d_in[3];
    const float* W_dec  = (const float*)d_in[4];
    const float* b_dec  = (const float*)d_in[5];
    const float* W_full = (const float*)d_in[6];
    // d_in[7] = b_full: softmax-invariant, unused.
    const float* W_beta = (const float*)d_in[8];
    const float* b_beta = (const float*)d_in[9];

    float* out = (float*)d_out;
    float* out_z = out;
    float* out_alpha = out + (size_t)BATCH * ENC;

    cudaFuncSetAttribute(att_gemm_mma, cudaFuncAttributeMaxDynamicSharedMemorySize, DYN_BYTES);

    prep_x<<<MROWS, 256>>>(x);
    prep_w<<<dim3(ENC / 64, ATTD / 64), 256>>>(W_enc);
    att2_kernel<<<BATCH, 256>>>(h, W_dec, b_dec, b_enc, W_beta, b_beta);
    att_gemm_mma<<<NCTA, 256, DYN_BYTES>>>(W_full);
    softmax_kernel<<<BATCH, 256>>>(out_alpha);
    z_kernel<<<dim3(ENC / 1024, BATCH), 256>>>(x, out_alpha, out_z);
}

// round 6
// speedup vs baseline: 1.0000x; 1.0000x over previous
#include <cuda_runtime.h>
#include <cuda_bf16.h>
#include <cstdint>
#include <math.h>

#define ENC 2048
#define DEC 512
#define ATTD 512
#define BATCH 256
#define LSEQ 196
#define MROWS (BATCH * LSEQ)      // 50176
#define TILE_M 128
#define NCTA (MROWS / TILE_M)     // 392
#define KBLK 32
#define NKB (ENC / KBLK)          // 64
#define NB_CHUNKS 2               // 512 / 256
#define NSTG 4
#define XSTG 16384                // 128 rows x 32k x 2B x 2(hi/lo)
#define WSTG 32768                // 256 rows x 32k x 2B x 2(hi/lo)
#define WBASE (NSTG * XSTG)       // 65536
#define DYN_BYTES (WBASE + NSTG * WSTG + 128)  // 196736
#define XLO_OFF ((size_t)MROWS * ENC * 2)      // byte offset of lo plane in g_Xc

// ---------------- scratch globals ----------------
__device__ float g_att2[BATCH * ATTD];
__device__ float g_gate[BATCH];
__device__ float g_att[MROWS];
// W transposed + bf16-split: [hl][n=512][k=2048] bf16
__device__ __align__(16) unsigned char g_Wt[2u * 512u * 2048u * 2u];
// x bf16-split: [hl][m=50176][k=2048] bf16 (hi plane then lo plane)
__device__ __align__(16) unsigned char g_Xc[2ull * MROWS * ENC * 2ull];

// ---------------- helpers ----------------
__device__ __forceinline__ uint32_t smem_u32(const void* p) {
    uint32_t a;
    asm("{ .reg .u64 t; cvta.to.shared.u64 t, %1; cvt.u32.u64 %0, t; }" : "=r"(a) : "l"(p));
    return a;
}
__device__ __forceinline__ uint32_t pack2(float a, float b) {
    __nv_bfloat162 t = __floats2bfloat162_rn(a, b);
    return *reinterpret_cast<uint32_t*>(&t);
}
#define LDSM_X4(r, addr) \
    asm volatile("ldmatrix.sync.aligned.m8n8.x4.shared.b16 {%0,%1,%2,%3}, [%4];" \
        : "=r"((r)[0]), "=r"((r)[1]), "=r"((r)[2]), "=r"((r)[3]) : "r"(addr))
#define MMA_BF16(c, a, b) \
    asm volatile("mma.sync.aligned.m16n8k16.row.col.f32.bf16.bf16.f32 " \
        "{%0,%1,%2,%3}, {%4,%5,%6,%7}, {%8,%9}, {%0,%1,%2,%3};" \
        : "+f"((c)[0]), "+f"((c)[1]), "+f"((c)[2]), "+f"((c)[3]) \
        : "r"((a)[0]), "r"((a)[1]), "r"((a)[2]), "r"((a)[3]), "r"((b)[0]), "r"((b)[1]))
#define CP_ASYNC16(dst, src) \
    asm volatile("cp.async.ca.shared.global [%0], [%1], 16;" :: "r"(dst), "l"(src) : "memory")
#define CP_COMMIT() asm volatile("cp.async.commit_group;" ::: "memory")
#define CP_WAIT2()  asm volatile("cp.async.wait_group 2;" ::: "memory")
#define CP_WAIT0()  asm volatile("cp.async.wait_group 0;" ::: "memory")

// ---------------------------------------------------------------------------
// prep_x: x fp32 [m][k] -> g_Xc bf16 hi/lo planes. One block per row.
// ---------------------------------------------------------------------------
__global__ __launch_bounds__(256) void prep_x(const float* __restrict__ x) {
    const size_t row = blockIdx.x;
    const int t = threadIdx.x;
    const float4* src = reinterpret_cast<const float4*>(x + row * ENC) + t * 2;
    float4 a = src[0], b = src[1];
    float e[8] = {a.x, a.y, a.z, a.w, b.x, b.y, b.z, b.w};
    uint32_t hw[4], lw[4];
#pragma unroll
    for (int q = 0; q < 4; q++) {
        float v0 = e[2 * q], v1 = e[2 * q + 1];
        float h0 = __bfloat162float(__float2bfloat16_rn(v0));
        float h1 = __bfloat162float(__float2bfloat16_rn(v1));
        hw[q] = pack2(h0, h1);
        lw[q] = pack2(v0 - h0, v1 - h1);
    }
    *reinterpret_cast<uint4*>(g_Xc + row * (ENC * 2) + t * 16) =
        make_uint4(hw[0], hw[1], hw[2], hw[3]);
    *reinterpret_cast<uint4*>(g_Xc + XLO_OFF + row * (ENC * 2) + t * 16) =
        make_uint4(lw[0], lw[1], lw[2], lw[3]);
}

// ---------------------------------------------------------------------------
// prep_w: W_enc [2048 k][512 n] fp32 -> g_Wt bf16 [hl][n][k]
// ---------------------------------------------------------------------------
__global__ __launch_bounds__(256) void prep_w(const float* __restrict__ W_enc) {
    __shared__ float tile[64][65];
    const int k0 = blockIdx.x * 64, n0 = blockIdx.y * 64;
    const int tid = threadIdx.x;
    for (int i = tid; i < 64 * 64; i += 256) {
        int kk = i >> 6, nn = i & 63;
        tile[kk][nn] = W_enc[(size_t)(k0 + kk) * ATTD + n0 + nn];
    }
    __syncthreads();
    for (int i = tid; i < 1024; i += 256) {
        int hl = i >> 9, rem = i & 511;
        int nn = rem >> 3, ch = rem & 7;
        uint32_t w[4];
#pragma unroll
        for (int j = 0; j < 4; j++) {
            float v0 = tile[ch * 8 + 2 * j][nn], v1 = tile[ch * 8 + 2 * j + 1][nn];
            float h0 = __bfloat162float(__float2bfloat16_rn(v0));
            float h1 = __bfloat162float(__float2bfloat16_rn(v1));
            w[j] = hl ? pack2(v0 - h0, v1 - h1) : pack2(h0, h1);
        }
        *reinterpret_cast<uint4*>(g_Wt + (size_t)hl * 2097152 +
                                  (size_t)(n0 + nn) * 4096 + (size_t)(k0 + ch * 8) * 2) =
            make_uint4(w[0], w[1], w[2], w[3]);
    }
}

// ---------------------------------------------------------------------------
// att2 + gate
// ---------------------------------------------------------------------------
__global__ __launch_bounds__(256) void att2_kernel(
    const float* __restrict__ h, const float* __restrict__ W_dec,
    const float* __restrict__ b_dec, const float* __restrict__ b_enc,
    const float* __restrict__ W_beta, const float* __restrict__ b_beta) {
    int b = blockIdx.x, t = threadIdx.x;
    __shared__ float hs[DEC];
    __shared__ float red[256];
    hs[t] = h[b * DEC + t];
    hs[t + 256] = h[b * DEC + t + 256];
    __syncthreads();
    float acc0 = 0.f, acc1 = 0.f;
#pragma unroll 8
    for (int k = 0; k < DEC; k++) {
        float hv = hs[k];
        acc0 += hv * W_dec[k * ATTD + t];
        acc1 += hv * W_dec[k * ATTD + t + 256];
    }
    g_att2[b * ATTD + t] = acc0 + b_dec[t] + b_enc[t];
    g_att2[b * ATTD + t + 256] = acc1 + b_dec[t + 256] + b_enc[t + 256];
    float p = hs[t] * W_beta[t] + hs[t + 256] * W_beta[t + 256];
    red[t] = p;
    __syncthreads();
    for (int s = 128; s > 0; s >>= 1) {
        if (t < s) red[t] += red[t + s];
        __syncthreads();
    }
    if (t == 0) g_gate[b] = 1.f / (1.f + expf(-(red[0] + b_beta[0])));
}

// ---------------------------------------------------------------------------
// Main GEMM: 3-pass bf16 mma.sync, 4-stage all-cp.async pipeline.
// 8 warps = 2(m) x 4(n); warp tile m64 x n64. MMAs grouped by pass so
// same-accumulator reuse distance is 8 HMMA issues (covers HMMA latency).
// ---------------------------------------------------------------------------
__global__ __launch_bounds__(256, 1) void att_gemm_mma(const float* __restrict__ W_full) {
    extern __shared__ unsigned char dynraw[];
    __shared__ float wf_s[ATTD];
    __shared__ float att_acc[TILE_M];

    const int tid = threadIdx.x;
    const int lane = tid & 31;
    const int wid = tid >> 5;
    const int wm = wid >> 2;   // 0..1
    const int wn = wid & 3;    // 0..3
    const int row0 = blockIdx.x * TILE_M;

    uint32_t rawb = smem_u32(dynraw);
    uint32_t dynb = (rawb + 127u) & ~127u;

    for (int i = tid; i < ATTD; i += 256) wf_s[i] = W_full[i];
    if (tid < TILE_M) att_acc[tid] = 0.f;
    __syncthreads();

    // ---- x loader: thread -> (row xm, k-half xh2 of 16 elems); 4 cp.async/stage ----
    const int xm = tid >> 1, xh2 = tid & 1;
    const int xsw = (xm >> 1) & 3;
    const size_t xrow_off = (size_t)(row0 + xm) * (ENC * 2);

    // ldmatrix lane geometry (2m x 4n)
    const int a_r = wm * 64 + (lane & 7) + (lane & 8);
    const int a_hi = lane >> 4;
    const int b_r = wn * 64 + (lane & 7) + ((lane >> 1) & 8);
    const int b_hi = (lane >> 3) & 1;

    for (int nb = 0; nb < NB_CHUNKS; nb++) {
        float acc[4][8][4];
#pragma unroll
        for (int mt = 0; mt < 4; mt++)
#pragma unroll
            for (int nt = 0; nt < 8; nt++)
#pragma unroll
                for (int q = 0; q < 4; q++) acc[mt][nt][q] = 0.f;

        // ---- prologue: stages 0..2 (x + W in one group per stage) ----
#pragma unroll
        for (int p = 0; p < 3; p++) {
#pragma unroll
            for (int hl = 0; hl < 2; hl++)
#pragma unroll
                for (int j = 0; j < 2; j++) {
                    int c = xh2 * 2 + j;
                    uint32_t dst = dynb + p * XSTG + hl * 8192 + xm * 64 +
                                   ((c ^ xsw) << 4);
                    const unsigned char* src = g_Xc + hl * XLO_OFF + xrow_off +
                        (size_t)(p * KBLK + c * 8) * 2;
                    CP_ASYNC16(dst, src);
                }
#pragma unroll
            for (int hl = 0; hl < 2; hl++)
#pragma unroll
                for (int j = 0; j < 4; j++) {
                    int i = tid + 256 * j;
                    int row = i >> 2, c = i & 3;
                    uint32_t dst = dynb + WBASE + p * WSTG + hl * 16384 +
                                   row * 64 + ((c ^ ((row >> 1) & 3)) << 4);
                    const unsigned char* src = g_Wt + (size_t)hl * 2097152 +
                        (size_t)(nb * 256 + row) * 4096 + (size_t)(p * KBLK + c * 8) * 2;
                    CP_ASYNC16(dst, src);
                }
            CP_COMMIT();
        }

        for (int kblk = 0; kblk < NKB; kblk++) {
            CP_WAIT2();
            __syncthreads();   // stage kblk%4 ready; stage (kblk+3)%4 free

            // issue x+W for stage kblk+3 (or empty group)
            if (kblk + 3 < NKB) {
                const int st = (kblk + 3) & 3;
#pragma unroll
                for (int hl = 0; hl < 2; hl++)
#pragma unroll
                    for (int j = 0; j < 2; j++) {
                        int c = xh2 * 2 + j;
                        uint32_t dst = dynb + st * XSTG + hl * 8192 + xm * 64 +
                                       ((c ^ xsw) << 4);
                        const unsigned char* src = g_Xc + hl * XLO_OFF + xrow_off +
                            (size_t)((kblk + 3) * KBLK + c * 8) * 2;
                        CP_ASYNC16(dst, src);
                    }
#pragma unroll
                for (int hl = 0; hl < 2; hl++)
#pragma unroll
                    for (int j = 0; j < 4; j++) {
                        int i = tid + 256 * j;
                        int row = i >> 2, c = i & 3;
                        uint32_t dst = dynb + WBASE + st * WSTG + hl * 16384 +
                                       row * 64 + ((c ^ ((row >> 1) & 3)) << 4);
                        const unsigned char* src = g_Wt + (size_t)hl * 2097152 +
                            (size_t)(nb * 256 + row) * 4096 +
                            (size_t)((kblk + 3) * KBLK + c * 8) * 2;
                        CP_ASYNC16(dst, src);
                    }
            }
            CP_COMMIT();

            // ---- MMA on stage kblk%4 (pass-grouped for dependency distance) ----
            {
                const uint32_t xsb = dynb + (kblk & 3) * XSTG;
                const uint32_t wsb = dynb + WBASE + (kblk & 3) * WSTG;
#pragma unroll
                for (int ks = 0; ks < 2; ks++) {
                    uint32_t ah[4][4], al[4][4];
#pragma unroll
                    for (int mt = 0; mt < 4; mt++) {
                        int row = a_r + mt * 16;
                        uint32_t ad = xsb + row * 64 +
                                      (((ks * 2 + a_hi) ^ ((row >> 1) & 3)) << 4);
                        LDSM_X4(ah[mt], ad);
                        LDSM_X4(al[mt], ad + 8192);
                    }
#pragma unroll
                    for (int ntp = 0; ntp < 4; ntp++) {
                        int row = b_r + ntp * 16;
                        uint32_t bd = wsb + row * 64 +
                                      (((ks * 2 + b_hi) ^ ((row >> 1) & 3)) << 4);
                        uint32_t bh[4], bl[4];
                        LDSM_X4(bh, bd);
                        LDSM_X4(bl, bd + 16384);
                        // pass 1: hi * hi  (8 distinct accumulators)
#pragma unroll
                        for (int mt = 0; mt < 4; mt++) {
                            MMA_BF16(acc[mt][2 * ntp],     ah[mt], bh + 0);
                            MMA_BF16(acc[mt][2 * ntp + 1], ah[mt], bh + 2);
                        }
                        // pass 2: hi * lo
#pragma unroll
                        for (int mt = 0; mt < 4; mt++) {
                            MMA_BF16(acc[mt][2 * ntp],     ah[mt], bl + 0);
                            MMA_BF16(acc[mt][2 * ntp + 1], ah[mt], bl + 2);
                        }
                        // pass 3: lo * hi
#pragma unroll
                        for (int mt = 0; mt < 4; mt++) {
                            MMA_BF16(acc[mt][2 * ntp],     al[mt], bh + 0);
                            MMA_BF16(acc[mt][2 * ntp + 1], al[mt], bh + 2);
                        }
                    }
                }
            }
        }
        CP_WAIT0();
        __syncthreads();

        // ---- epilogue for this n-chunk ----
#pragma unroll
        for (int mt = 0; mt < 4; mt++)
#pragma unroll
            for (int rh = 0; rh < 2; rh++) {
                int ml = wm * 64 + mt * 16 + (lane >> 2) + rh * 8;
                int gm = row0 + ml;
                int b = gm / LSEQ;
                const float* a2 = g_att2 + (size_t)b * ATTD + nb * 256 + wn * 64;
                const float* wfp = wf_s + nb * 256 + wn * 64;
                float s = 0.f;
#pragma unroll
                for (int nt = 0; nt < 8; nt++) {
#pragma unroll
                    for (int e2 = 0; e2 < 2; e2++) {
                        int nn = nt * 8 + (lane & 3) * 2 + e2;
                        float v = acc[mt][nt][rh * 2 + e2] + __ldg(a2 + nn);
                        s += fmaxf(v, 0.f) * wfp[nn];
                    }
                }
                s += __shfl_xor_sync(0xFFFFFFFF, s, 1);
                s += __shfl_xor_sync(0xFFFFFFFF, s, 2);
                if ((lane & 3) == 0) atomicAdd(&att_acc[ml], s);
            }
        __syncthreads();
    }

    if (tid < TILE_M) g_att[row0 + tid] = att_acc[tid];
}

// ---------------------------------------------------------------------------
__global__ __launch_bounds__(256) void softmax_kernel(float* __restrict__ out_alpha) {
    int b = blockIdx.x, t = threadIdx.x;
    __shared__ float sred[256];
    float v = (t < LSEQ) ? g_att[b * LSEQ + t] : -1e30f;
    sred[t] = v;
    __syncthreads();
    for (int s = 128; s > 0; s >>= 1) {
        if (t < s) sred[t] = fmaxf(sred[t], sred[t + s]);
        __syncthreads();
    }
    float m = sred[0];
    __syncthreads();
    float e = (t < LSEQ) ? expf(v - m) : 0.f;
    sred[t] = e;
    __syncthreads();
    for (int s = 128; s > 0; s >>= 1) {
        if (t < s) sred[t] += sred[t + s];
        __syncthreads();
    }
    float inv = 1.f / sred[0];
    if (t < LSEQ) out_alpha[b * LSEQ + t] = e * inv;
}

__global__ __launch_bounds__(256) void z_kernel(
    const float* __restrict__ x, const float* __restrict__ alpha,
    float* __restrict__ out_z) {
    int b = blockIdx.y;
    int c4 = blockIdx.x * 256 + threadIdx.x;
    __shared__ float sal[LSEQ];
    for (int i = threadIdx.x; i < LSEQ; i += 256) sal[i] = alpha[b * LSEQ + i];
    __syncthreads();
    const float4* xp = reinterpret_cast<const float4*>(x + (size_t)b * LSEQ * ENC) + c4;
    float ax = 0.f, ay = 0.f, az = 0.f, aw = 0.f;
#pragma unroll 4
    for (int l = 0; l < LSEQ; l++) {
        float4 v = xp[(size_t)l * (ENC / 4)];
        float a = sal[l];
        ax += a * v.x; ay += a * v.y; az += a * v.z; aw += a * v.w;
    }
    float g = g_gate[b];
    float4 o;
    o.x = g * ax; o.y = g * ay; o.z = g * az; o.w = g * aw;
    reinterpret_cast<float4*>(out_z)[(size_t)b * (ENC / 4) + c4] = o;
}

// ---------------------------------------------------------------------------
extern "C" void kernel_launch(void* const* d_in, const int* in_sizes, int n_in,
                              void* d_out, int out_size) {
    const float* x      = (const float*)d_in[0];
    const float* h      = (const float*)d_in[1];
    const float* W_enc  = (const float*)d_in[2];
    const float* b_enc  = (const float*)d_in[3];
    const float* W_dec  = (const float*)d_in[4];
    const float* b_dec  = (const float*)d_in[5];
    const float* W_full = (const float*)d_in[6];
    // d_in[7] = b_full: softmax-invariant, unused.
    const float* W_beta = (const float*)d_in[8];
    const float* b_beta = (const float*)d_in[9];

    float* out = (float*)d_out;
    float* out_z = out;
    float* out_alpha = out + (size_t)BATCH * ENC;

    cudaFuncSetAttribute(att_gemm_mma, cudaFuncAttributeMaxDynamicSharedMemorySize, DYN_BYTES);

    prep_x<<<MROWS, 256>>>(x);
    prep_w<<<dim3(ENC / 64, ATTD / 64), 256>>>(W_enc);
    att2_kernel<<<BATCH, 256>>>(h, W_dec, b_dec, b_enc, W_beta, b_beta);
    att_gemm_mma<<<NCTA, 256, DYN_BYTES>>>(W_full);
    softmax_kernel<<<BATCH, 256>>>(out_alpha);
    z_kernel<<<dim3(ENC / 1024, BATCH), 256>>>(x, out_alpha, out_z);
}